// round 1
// baseline (speedup 1.0000x reference)
#include <cuda_runtime.h>

#define TPB    256
#define M_BLK  16
#define KDIM   4096
#define NDIM   4096
#define RANK   8

__device__ __forceinline__ float4 f4fma(float s, float4 a, float4 acc) {
    acc.x = fmaf(s, a.x, acc.x);
    acc.y = fmaf(s, a.y, acc.y);
    acc.z = fmaf(s, a.z, acc.z);
    acc.w = fmaf(s, a.w, acc.w);
    return acc;
}

__device__ __forceinline__ float4 warp_red(float4 v) {
    #pragma unroll
    for (int s = 16; s > 0; s >>= 1) {
        v.x += __shfl_xor_sync(0xFFFFFFFFu, v.x, s);
        v.y += __shfl_xor_sync(0xFFFFFFFFu, v.y, s);
        v.z += __shfl_xor_sync(0xFFFFFFFFu, v.z, s);
        v.w += __shfl_xor_sync(0xFFFFFFFFu, v.w, s);
    }
    return v;
}

__global__ __launch_bounds__(TPB, 2)
void lora_fused_kernel(const float* __restrict__ x,
                       const float* __restrict__ A,
                       const float* __restrict__ B,
                       float* __restrict__ out)
{
    __shared__ float t_s[M_BLK][RANK];      // t = 2 * (x_rows @ B)
    __shared__ float part[4][8][32];        // [group][warp][m*8+r]

    const int tid  = threadIdx.x;
    const int lane = tid & 31;
    const int warp = tid >> 5;
    const size_t row0 = (size_t)blockIdx.x * M_BLK;

    const float4* __restrict__ x4 = (const float4*)x;   // row stride 1024 f4
    const float4* __restrict__ B4 = (const float4*)B;   // B[k][r] @ k*8+r
    const float4* __restrict__ A4 = (const float4*)A;   // A[r][n] @ r*4096+n
    float4* __restrict__ out4 = (float4*)out;

    // ---------------- Phase 1: t = x_rows @ B ----------------
    #pragma unroll
    for (int g = 0; g < 4; ++g) {
        float4 aLo[4], aHi[4];
        #pragma unroll
        for (int m = 0; m < 4; ++m) {
            aLo[m] = make_float4(0.f, 0.f, 0.f, 0.f);
            aHi[m] = make_float4(0.f, 0.f, 0.f, 0.f);
        }

        #pragma unroll
        for (int j = 0; j < 4; ++j) {
            const int p = tid + j * TPB;              // float4 pos in row (0..1023)
            const float4* Bp = B4 + (size_t)p * 8;    // B rows 4p..4p+3, all 8 r
            const float4 b0 = Bp[0], b1 = Bp[1], b2 = Bp[2], b3 = Bp[3];
            const float4 b4 = Bp[4], b5 = Bp[5], b6 = Bp[6], b7 = Bp[7];
            #pragma unroll
            for (int m = 0; m < 4; ++m) {
                const float4 xv = x4[(row0 + g * 4 + m) * (KDIM / 4) + p];
                aLo[m] = f4fma(xv.x, b0, aLo[m]);  aHi[m] = f4fma(xv.x, b1, aHi[m]);
                aLo[m] = f4fma(xv.y, b2, aLo[m]);  aHi[m] = f4fma(xv.y, b3, aHi[m]);
                aLo[m] = f4fma(xv.z, b4, aLo[m]);  aHi[m] = f4fma(xv.z, b5, aHi[m]);
                aLo[m] = f4fma(xv.w, b6, aLo[m]);  aHi[m] = f4fma(xv.w, b7, aHi[m]);
            }
        }

        #pragma unroll
        for (int m = 0; m < 4; ++m) {
            aLo[m] = warp_red(aLo[m]);
            aHi[m] = warp_red(aHi[m]);
        }
        if (lane == 0) {
            #pragma unroll
            for (int m = 0; m < 4; ++m) {
                part[g][warp][m * 8 + 0] = aLo[m].x;
                part[g][warp][m * 8 + 1] = aLo[m].y;
                part[g][warp][m * 8 + 2] = aLo[m].z;
                part[g][warp][m * 8 + 3] = aLo[m].w;
                part[g][warp][m * 8 + 4] = aHi[m].x;
                part[g][warp][m * 8 + 5] = aHi[m].y;
                part[g][warp][m * 8 + 6] = aHi[m].z;
                part[g][warp][m * 8 + 7] = aHi[m].w;
            }
        }
    }
    __syncthreads();

    if (tid < 128) {
        const int g = tid >> 5, v = tid & 31;
        float s = 0.f;
        #pragma unroll
        for (int w = 0; w < 8; ++w) s += part[g][w][v];
        t_s[g * 4 + (v >> 3)][v & 7] = 2.0f * s;   // fold SCALING here
    }
    __syncthreads();

    // ---------------- Phase 2: out = t @ A ----------------
    #pragma unroll
    for (int j = 0; j < 4; ++j) {
        const int p = tid + j * TPB;                 // out float4 col (0..1023)
        const float4 a0 = A4[0 * 1024 + p];
        const float4 a1 = A4[1 * 1024 + p];
        const float4 a2 = A4[2 * 1024 + p];
        const float4 a3 = A4[3 * 1024 + p];
        const float4 a4 = A4[4 * 1024 + p];
        const float4 a5 = A4[5 * 1024 + p];
        const float4 a6 = A4[6 * 1024 + p];
        const float4 a7 = A4[7 * 1024 + p];

        #pragma unroll
        for (int m = 0; m < M_BLK; ++m) {
            const float4 t01 = *(const float4*)&t_s[m][0];
            const float4 t23 = *(const float4*)&t_s[m][4];
            float4 o = make_float4(0.f, 0.f, 0.f, 0.f);
            o = f4fma(t01.x, a0, o);
            o = f4fma(t01.y, a1, o);
            o = f4fma(t01.z, a2, o);
            o = f4fma(t01.w, a3, o);
            o = f4fma(t23.x, a4, o);
            o = f4fma(t23.y, a5, o);
            o = f4fma(t23.z, a6, o);
            o = f4fma(t23.w, a7, o);
            out4[(row0 + m) * (NDIM / 4) + p] = o;
        }
    }
}

extern "C" void kernel_launch(void* const* d_in, const int* in_sizes, int n_in,
                              void* d_out, int out_size)
{
    const float* x = (const float*)d_in[0];   // [4,4096,4096]
    const float* A = (const float*)d_in[1];   // [8,4096]
    const float* B = (const float*)d_in[2];   // [4096,8]
    float* out = (float*)d_out;               // [4,4096,4096] fp32

    const int total_rows = 4 * 4096;          // 16384
    dim3 grid(total_rows / M_BLK);            // 1024
    lora_fused_kernel<<<grid, TPB>>>(x, A, B, out);
}

// round 2
// speedup vs baseline: 1.8266x; 1.8266x over previous
#include <cuda_runtime.h>

#define TPB          256
#define ROWS_PER_BLK 8
#define KDIM         4096
#define KD4          1024      // KDIM/4
#define NDIM         4096
#define ND4          1024
#define RANK         8

// B transposed: BT[r][k] = B[k][r]  (128 KB, L2/L1 resident)
__device__ float BT_g[RANK * KDIM];

__global__ void transpose_B_kernel(const float* __restrict__ B)
{
    int o = blockIdx.x * blockDim.x + threadIdx.x;   // 0..32767, coalesced write
    int r = o >> 12;                                 // o / 4096
    int k = o & (KDIM - 1);
    BT_g[o] = B[k * RANK + r];
}

__device__ __forceinline__ float4 f4fma(float s, float4 a, float4 acc) {
    acc.x = fmaf(s, a.x, acc.x);
    acc.y = fmaf(s, a.y, acc.y);
    acc.z = fmaf(s, a.z, acc.z);
    acc.w = fmaf(s, a.w, acc.w);
    return acc;
}

__global__ __launch_bounds__(TPB, 3)
void lora_fused2_kernel(const float* __restrict__ x,
                        const float* __restrict__ A,
                        float* __restrict__ out)
{
    __shared__ float t_s[ROWS_PER_BLK][RANK];   // t = 2 * (x_rows @ B)

    const int tid  = threadIdx.x;
    const int lane = tid & 31;
    const int warp = tid >> 5;
    const size_t row0 = (size_t)blockIdx.x * ROWS_PER_BLK;

    const float4* __restrict__ x4  = (const float4*)x;
    const float4* __restrict__ A4  = (const float4*)A;     // A[r][n], coalesced
    const float4* __restrict__ BT4 = (const float4*)BT_g;  // BT[r][k], coalesced
    float4* __restrict__ out4 = (float4*)out;

    // ---------------- Phase 1: one row per warp ----------------
    {
        const size_t row = row0 + warp;
        const float4* __restrict__ xr = x4 + row * KD4;

        float acc0 = 0.f, acc1 = 0.f, acc2 = 0.f, acc3 = 0.f;
        float acc4 = 0.f, acc5 = 0.f, acc6 = 0.f, acc7 = 0.f;

        #pragma unroll 4
        for (int i = 0; i < 32; ++i) {
            const int p = i * 32 + lane;             // coalesced
            const float4 xv = __ldcs(xr + p);        // streamed, evict-first

            float4 b;
            b = BT4[0 * KD4 + p];
            acc0 = fmaf(xv.x, b.x, acc0); acc0 = fmaf(xv.y, b.y, acc0);
            acc0 = fmaf(xv.z, b.z, acc0); acc0 = fmaf(xv.w, b.w, acc0);
            b = BT4[1 * KD4 + p];
            acc1 = fmaf(xv.x, b.x, acc1); acc1 = fmaf(xv.y, b.y, acc1);
            acc1 = fmaf(xv.z, b.z, acc1); acc1 = fmaf(xv.w, b.w, acc1);
            b = BT4[2 * KD4 + p];
            acc2 = fmaf(xv.x, b.x, acc2); acc2 = fmaf(xv.y, b.y, acc2);
            acc2 = fmaf(xv.z, b.z, acc2); acc2 = fmaf(xv.w, b.w, acc2);
            b = BT4[3 * KD4 + p];
            acc3 = fmaf(xv.x, b.x, acc3); acc3 = fmaf(xv.y, b.y, acc3);
            acc3 = fmaf(xv.z, b.z, acc3); acc3 = fmaf(xv.w, b.w, acc3);
            b = BT4[4 * KD4 + p];
            acc4 = fmaf(xv.x, b.x, acc4); acc4 = fmaf(xv.y, b.y, acc4);
            acc4 = fmaf(xv.z, b.z, acc4); acc4 = fmaf(xv.w, b.w, acc4);
            b = BT4[5 * KD4 + p];
            acc5 = fmaf(xv.x, b.x, acc5); acc5 = fmaf(xv.y, b.y, acc5);
            acc5 = fmaf(xv.z, b.z, acc5); acc5 = fmaf(xv.w, b.w, acc5);
            b = BT4[6 * KD4 + p];
            acc6 = fmaf(xv.x, b.x, acc6); acc6 = fmaf(xv.y, b.y, acc6);
            acc6 = fmaf(xv.z, b.z, acc6); acc6 = fmaf(xv.w, b.w, acc6);
            b = BT4[7 * KD4 + p];
            acc7 = fmaf(xv.x, b.x, acc7); acc7 = fmaf(xv.y, b.y, acc7);
            acc7 = fmaf(xv.z, b.z, acc7); acc7 = fmaf(xv.w, b.w, acc7);
        }

        #pragma unroll
        for (int s = 16; s; s >>= 1) {
            acc0 += __shfl_xor_sync(0xFFFFFFFFu, acc0, s);
            acc1 += __shfl_xor_sync(0xFFFFFFFFu, acc1, s);
            acc2 += __shfl_xor_sync(0xFFFFFFFFu, acc2, s);
            acc3 += __shfl_xor_sync(0xFFFFFFFFu, acc3, s);
            acc4 += __shfl_xor_sync(0xFFFFFFFFu, acc4, s);
            acc5 += __shfl_xor_sync(0xFFFFFFFFu, acc5, s);
            acc6 += __shfl_xor_sync(0xFFFFFFFFu, acc6, s);
            acc7 += __shfl_xor_sync(0xFFFFFFFFu, acc7, s);
        }
        if (lane == 0) {
            t_s[warp][0] = 2.0f * acc0;  t_s[warp][1] = 2.0f * acc1;
            t_s[warp][2] = 2.0f * acc2;  t_s[warp][3] = 2.0f * acc3;
            t_s[warp][4] = 2.0f * acc4;  t_s[warp][5] = 2.0f * acc5;
            t_s[warp][6] = 2.0f * acc6;  t_s[warp][7] = 2.0f * acc7;
        }
    }
    __syncthreads();

    // ---------------- Phase 2: out = t @ A (coalesced) ----------------
    #pragma unroll
    for (int j = 0; j < 4; ++j) {
        const int p = tid + j * TPB;                 // out float4 col (0..1023)
        const float4 a0 = A4[0 * ND4 + p];
        const float4 a1 = A4[1 * ND4 + p];
        const float4 a2 = A4[2 * ND4 + p];
        const float4 a3 = A4[3 * ND4 + p];
        const float4 a4 = A4[4 * ND4 + p];
        const float4 a5 = A4[5 * ND4 + p];
        const float4 a6 = A4[6 * ND4 + p];
        const float4 a7 = A4[7 * ND4 + p];

        #pragma unroll
        for (int m = 0; m < ROWS_PER_BLK; ++m) {
            const float4 t01 = *(const float4*)&t_s[m][0];
            const float4 t23 = *(const float4*)&t_s[m][4];
            float4 o = make_float4(0.f, 0.f, 0.f, 0.f);
            o = f4fma(t01.x, a0, o);
            o = f4fma(t01.y, a1, o);
            o = f4fma(t01.z, a2, o);
            o = f4fma(t01.w, a3, o);
            o = f4fma(t23.x, a4, o);
            o = f4fma(t23.y, a5, o);
            o = f4fma(t23.z, a6, o);
            o = f4fma(t23.w, a7, o);
            out4[(row0 + m) * ND4 + p] = o;
        }
    }
}

extern "C" void kernel_launch(void* const* d_in, const int* in_sizes, int n_in,
                              void* d_out, int out_size)
{
    const float* x = (const float*)d_in[0];   // [4,4096,4096]
    const float* A = (const float*)d_in[1];   // [8,4096]
    const float* B = (const float*)d_in[2];   // [4096,8]
    float* out = (float*)d_out;               // [4,4096,4096] fp32

    transpose_B_kernel<<<(RANK * KDIM) / TPB, TPB>>>(B);

    const int total_rows = 4 * 4096;                  // 16384
    dim3 grid(total_rows / ROWS_PER_BLK);             // 2048
    lora_fused2_kernel<<<grid, TPB>>>(x, A, out);
}

// round 3
// speedup vs baseline: 2.2701x; 1.2428x over previous
#include <cuda_runtime.h>

#define TPB            256
#define WARPS          8
#define ROWS_PER_WARP  4
#define ROWS_PER_BLK   (WARPS * ROWS_PER_WARP)   // 32
#define KDIM           4096
#define KD4            1024
#define ND4            1024
#define RANK           8

typedef unsigned long long u64;

// B transposed: BT[r][k] = B[k][r]  (128 KB, L1/L2 resident)
__device__ float BT_g[RANK * KDIM];

__global__ void transpose_B_kernel(const float* __restrict__ B)
{
    int o = blockIdx.x * blockDim.x + threadIdx.x;
    int r = o >> 12;
    int k = o & (KDIM - 1);
    BT_g[o] = B[k * RANK + r];
}

__device__ __forceinline__ u64 pack2(float lo, float hi) {
    u64 d; asm("mov.b64 %0, {%1,%2};" : "=l"(d) : "f"(lo), "f"(hi)); return d;
}
__device__ __forceinline__ void fma2(u64 &d, u64 a, u64 b) {
    asm("fma.rn.f32x2 %0, %1, %2, %0;" : "+l"(d) : "l"(a), "l"(b));
}
__device__ __forceinline__ u64 add2(u64 a, u64 b) {
    u64 d; asm("add.rn.f32x2 %0, %1, %2;" : "=l"(d) : "l"(a), "l"(b)); return d;
}
__device__ __forceinline__ float2 unpack2(u64 v) {
    float2 f; asm("mov.b64 {%0,%1}, %2;" : "=f"(f.x), "=f"(f.y) : "l"(v)); return f;
}

__global__ __launch_bounds__(TPB, 2)
void lora_fused3_kernel(const float* __restrict__ x,
                        const float* __restrict__ A,
                        float* __restrict__ out)
{
    __shared__ u64 t2_s[ROWS_PER_BLK][RANK];   // {2t, 2t} broadcast pairs

    const int tid  = threadIdx.x;
    const int lane = tid & 31;
    const int warp = tid >> 5;
    const size_t row0 = (size_t)blockIdx.x * ROWS_PER_BLK;

    const float4* __restrict__ x4  = (const float4*)x;
    const float4* __restrict__ A4  = (const float4*)A;
    const float4* __restrict__ BT4 = (const float4*)BT_g;
    float4* __restrict__ out4 = (float4*)out;

    // ---------------- Phase 1: 4 rows per warp, BT amortized ----------------
    {
        const size_t rowW = row0 + (size_t)warp * ROWS_PER_WARP;
        const float4* __restrict__ xr0 = x4 + (rowW + 0) * KD4;
        const float4* __restrict__ xr1 = x4 + (rowW + 1) * KD4;
        const float4* __restrict__ xr2 = x4 + (rowW + 2) * KD4;
        const float4* __restrict__ xr3 = x4 + (rowW + 3) * KD4;

        u64 acc[ROWS_PER_WARP][RANK];
        #pragma unroll
        for (int m = 0; m < ROWS_PER_WARP; ++m)
            #pragma unroll
            for (int r = 0; r < RANK; ++r)
                acc[m][r] = 0ull;

        #pragma unroll 2
        for (int i = 0; i < 32; ++i) {
            const int p = i * 32 + lane;

            const float4 xv0 = __ldcs(xr0 + p);
            const float4 xv1 = __ldcs(xr1 + p);
            const float4 xv2 = __ldcs(xr2 + p);
            const float4 xv3 = __ldcs(xr3 + p);

            u64 xlo[4], xhi[4];
            xlo[0] = pack2(xv0.x, xv0.y);  xhi[0] = pack2(xv0.z, xv0.w);
            xlo[1] = pack2(xv1.x, xv1.y);  xhi[1] = pack2(xv1.z, xv1.w);
            xlo[2] = pack2(xv2.x, xv2.y);  xhi[2] = pack2(xv2.z, xv2.w);
            xlo[3] = pack2(xv3.x, xv3.y);  xhi[3] = pack2(xv3.z, xv3.w);

            #pragma unroll
            for (int r = 0; r < RANK; ++r) {
                const float4 b = BT4[r * KD4 + p];
                const u64 blo = pack2(b.x, b.y);
                const u64 bhi = pack2(b.z, b.w);
                #pragma unroll
                for (int m = 0; m < ROWS_PER_WARP; ++m) {
                    fma2(acc[m][r], xlo[m], blo);
                    fma2(acc[m][r], xhi[m], bhi);
                }
            }
        }

        // warp reduction on packed pairs
        #pragma unroll
        for (int s = 16; s; s >>= 1) {
            #pragma unroll
            for (int m = 0; m < ROWS_PER_WARP; ++m)
                #pragma unroll
                for (int r = 0; r < RANK; ++r)
                    acc[m][r] = add2(acc[m][r],
                                     __shfl_xor_sync(0xFFFFFFFFu, acc[m][r], s));
        }
        if (lane == 0) {
            #pragma unroll
            for (int m = 0; m < ROWS_PER_WARP; ++m)
                #pragma unroll
                for (int r = 0; r < RANK; ++r) {
                    const float2 f = unpack2(acc[m][r]);
                    const float t = 2.0f * (f.x + f.y);   // fold SCALING
                    t2_s[warp * ROWS_PER_WARP + m][r] = pack2(t, t);
                }
        }
    }
    __syncthreads();

    // ---------------- Phase 2: out = t @ A, packed f32x2 ----------------
    #pragma unroll
    for (int j = 0; j < 4; ++j) {
        const int p = tid + j * TPB;                 // out float4 col (0..1023)
        u64 alo[RANK], ahi[RANK];
        #pragma unroll
        for (int r = 0; r < RANK; ++r) {
            const float4 a = A4[r * ND4 + p];
            alo[r] = pack2(a.x, a.y);
            ahi[r] = pack2(a.z, a.w);
        }

        #pragma unroll 4
        for (int m = 0; m < ROWS_PER_BLK; ++m) {
            const ulonglong2* __restrict__ tp2 = (const ulonglong2*)t2_s[m];
            const ulonglong2 t01 = tp2[0];   // {t0,t0},{t1,t1}
            const ulonglong2 t23 = tp2[1];
            const ulonglong2 t45 = tp2[2];
            const ulonglong2 t67 = tp2[3];

            u64 olo = 0ull, ohi = 0ull;
            fma2(olo, t01.x, alo[0]);  fma2(ohi, t01.x, ahi[0]);
            fma2(olo, t01.y, alo[1]);  fma2(ohi, t01.y, ahi[1]);
            fma2(olo, t23.x, alo[2]);  fma2(ohi, t23.x, ahi[2]);
            fma2(olo, t23.y, alo[3]);  fma2(ohi, t23.y, ahi[3]);
            fma2(olo, t45.x, alo[4]);  fma2(ohi, t45.x, ahi[4]);
            fma2(olo, t45.y, alo[5]);  fma2(ohi, t45.y, ahi[5]);
            fma2(olo, t67.x, alo[6]);  fma2(ohi, t67.x, ahi[6]);
            fma2(olo, t67.y, alo[7]);  fma2(ohi, t67.y, ahi[7]);

            const float2 f0 = unpack2(olo);
            const float2 f1 = unpack2(ohi);
            out4[(row0 + m) * ND4 + p] = make_float4(f0.x, f0.y, f1.x, f1.y);
        }
    }
}

extern "C" void kernel_launch(void* const* d_in, const int* in_sizes, int n_in,
                              void* d_out, int out_size)
{
    const float* x = (const float*)d_in[0];   // [4,4096,4096]
    const float* A = (const float*)d_in[1];   // [8,4096]
    const float* B = (const float*)d_in[2];   // [4096,8]
    float* out = (float*)d_out;               // [4,4096,4096] fp32

    transpose_B_kernel<<<(RANK * KDIM) / TPB, TPB>>>(B);

    const int total_rows = 4 * 4096;                  // 16384
    dim3 grid(total_rows / ROWS_PER_BLK);             // 512
    lora_fused3_kernel<<<grid, TPB>>>(x, A, out);
}

// round 4
// speedup vs baseline: 2.3529x; 1.0365x over previous
#include <cuda_runtime.h>

#define TPB            256
#define WARPS          8
#define ROWS_PER_WARP  8
#define ROWS_PER_BLK   (WARPS * ROWS_PER_WARP)   // 64
#define KDIM           4096
#define KD4            1024
#define ND4            1024
#define RANK           8

typedef unsigned long long u64;

// BP[rp][k] = { B[k][2rp], B[k][2rp+1] }   (4 x 4096 u64 = 128 KB)
__device__ u64 BP_g[4 * KDIM];

__global__ void pack_B_kernel(const float* __restrict__ B)
{
    int o = blockIdx.x * blockDim.x + threadIdx.x;   // 0..16383
    int rp = o >> 12;                                // o / 4096
    int k  = o & (KDIM - 1);
    BP_g[o] = ((const u64*)B)[k * 4 + rp];
}

__device__ __forceinline__ u64 pack2(float lo, float hi) {
    u64 d; asm("mov.b64 %0, {%1,%2};" : "=l"(d) : "f"(lo), "f"(hi)); return d;
}
__device__ __forceinline__ void fma2(u64 &d, u64 a, u64 b) {
    asm("fma.rn.f32x2 %0, %1, %2, %0;" : "+l"(d) : "l"(a), "l"(b));
}
__device__ __forceinline__ u64 add2(u64 a, u64 b) {
    u64 d; asm("add.rn.f32x2 %0, %1, %2;" : "=l"(d) : "l"(a), "l"(b)); return d;
}
__device__ __forceinline__ float2 unpack2(u64 v) {
    float2 f; asm("mov.b64 {%0,%1}, %2;" : "=f"(f.x), "=f"(f.y) : "l"(v)); return f;
}

__global__ __launch_bounds__(TPB, 2)
void lora_fused4_kernel(const float* __restrict__ x,
                        const float* __restrict__ A,
                        float* __restrict__ out)
{
    __shared__ u64 t2_s[ROWS_PER_BLK][RANK];   // {2t, 2t} broadcast pairs

    const int tid  = threadIdx.x;
    const int lane = tid & 31;
    const int warp = tid >> 5;
    const size_t row0 = (size_t)blockIdx.x * ROWS_PER_BLK;

    const float4* __restrict__ x4   = (const float4*)x;
    const float4* __restrict__ A4   = (const float4*)A;
    const ulonglong2* __restrict__ BP2 = (const ulonglong2*)BP_g; // 2048 per rp-row
    float4* __restrict__ out4 = (float4*)out;

    // ---------------- Phase 1: 8 rows per warp, r-paired B ----------------
    {
        const size_t rowW = row0 + (size_t)warp * ROWS_PER_WARP;
        const float4* __restrict__ xr = x4 + rowW * KD4;

        u64 acc[ROWS_PER_WARP][4];    // acc[m][rp] = {t[2rp], t[2rp+1]} partial
        #pragma unroll
        for (int m = 0; m < ROWS_PER_WARP; ++m)
            #pragma unroll
            for (int rp = 0; rp < 4; ++rp)
                acc[m][rp] = 0ull;

        for (int i = 0; i < 32; ++i) {
            const int p = i * 32 + lane;

            // B pairs for this lane's 4 k-values (shared by all 8 rows)
            ulonglong2 bp[4][2];
            #pragma unroll
            for (int rp = 0; rp < 4; ++rp) {
                bp[rp][0] = BP2[rp * 2048 + 2 * p + 0];   // k=4p+0, 4p+1
                bp[rp][1] = BP2[rp * 2048 + 2 * p + 1];   // k=4p+2, 4p+3
            }

            // two half-steps of 4 rows to bound register pressure
            #pragma unroll
            for (int h = 0; h < 2; ++h) {
                float4 xv[4];
                #pragma unroll
                for (int q = 0; q < 4; ++q)
                    xv[q] = __ldcs(xr + (h * 4 + q) * KD4 + p);

                #pragma unroll
                for (int q = 0; q < 4; ++q) {
                    const int m = h * 4 + q;
                    const u64 xb0 = pack2(xv[q].x, xv[q].x);
                    const u64 xb1 = pack2(xv[q].y, xv[q].y);
                    const u64 xb2 = pack2(xv[q].z, xv[q].z);
                    const u64 xb3 = pack2(xv[q].w, xv[q].w);
                    #pragma unroll
                    for (int rp = 0; rp < 4; ++rp) {
                        fma2(acc[m][rp], xb0, bp[rp][0].x);
                        fma2(acc[m][rp], xb1, bp[rp][0].y);
                        fma2(acc[m][rp], xb2, bp[rp][1].x);
                        fma2(acc[m][rp], xb3, bp[rp][1].y);
                    }
                }
            }
        }

        // warp reduction on packed pairs
        #pragma unroll
        for (int s = 16; s; s >>= 1) {
            #pragma unroll
            for (int m = 0; m < ROWS_PER_WARP; ++m)
                #pragma unroll
                for (int rp = 0; rp < 4; ++rp)
                    acc[m][rp] = add2(acc[m][rp],
                                      __shfl_xor_sync(0xFFFFFFFFu, acc[m][rp], s));
        }
        if (lane == 0) {
            #pragma unroll
            for (int m = 0; m < ROWS_PER_WARP; ++m)
                #pragma unroll
                for (int rp = 0; rp < 4; ++rp) {
                    const float2 f = unpack2(acc[m][rp]);
                    const float tA = 2.0f * f.x;          // fold SCALING
                    const float tB = 2.0f * f.y;
                    t2_s[warp * ROWS_PER_WARP + m][2 * rp + 0] = pack2(tA, tA);
                    t2_s[warp * ROWS_PER_WARP + m][2 * rp + 1] = pack2(tB, tB);
                }
        }
    }
    __syncthreads();

    // ---------------- Phase 2: out = t @ A, packed f32x2 ----------------
    #pragma unroll
    for (int j = 0; j < 4; ++j) {
        const int p = tid + j * TPB;                 // out float4 col (0..1023)
        u64 alo[RANK], ahi[RANK];
        #pragma unroll
        for (int r = 0; r < RANK; ++r) {
            const float4 a = A4[r * ND4 + p];
            alo[r] = pack2(a.x, a.y);
            ahi[r] = pack2(a.z, a.w);
        }

        #pragma unroll 4
        for (int m = 0; m < ROWS_PER_BLK; ++m) {
            const ulonglong2* __restrict__ tp2 = (const ulonglong2*)t2_s[m];
            const ulonglong2 t01 = tp2[0];
            const ulonglong2 t23 = tp2[1];
            const ulonglong2 t45 = tp2[2];
            const ulonglong2 t67 = tp2[3];

            u64 olo = 0ull, ohi = 0ull;
            fma2(olo, t01.x, alo[0]);  fma2(ohi, t01.x, ahi[0]);
            fma2(olo, t01.y, alo[1]);  fma2(ohi, t01.y, ahi[1]);
            fma2(olo, t23.x, alo[2]);  fma2(ohi, t23.x, ahi[2]);
            fma2(olo, t23.y, alo[3]);  fma2(ohi, t23.y, ahi[3]);
            fma2(olo, t45.x, alo[4]);  fma2(ohi, t45.x, ahi[4]);
            fma2(olo, t45.y, alo[5]);  fma2(ohi, t45.y, ahi[5]);
            fma2(olo, t67.x, alo[6]);  fma2(ohi, t67.x, ahi[6]);
            fma2(olo, t67.y, alo[7]);  fma2(ohi, t67.y, ahi[7]);

            const float2 f0 = unpack2(olo);
            const float2 f1 = unpack2(ohi);
            out4[(row0 + m) * ND4 + p] = make_float4(f0.x, f0.y, f1.x, f1.y);
        }
    }
}

extern "C" void kernel_launch(void* const* d_in, const int* in_sizes, int n_in,
                              void* d_out, int out_size)
{
    const float* x = (const float*)d_in[0];   // [4,4096,4096]
    const float* A = (const float*)d_in[1];   // [8,4096]
    const float* B = (const float*)d_in[2];   // [4096,8]
    float* out = (float*)d_out;               // [4,4096,4096] fp32

    pack_B_kernel<<<(4 * KDIM) / TPB, TPB>>>(B);

    const int total_rows = 4 * 4096;                  // 16384
    dim3 grid(total_rows / ROWS_PER_BLK);             // 256
    lora_fused4_kernel<<<grid, TPB>>>(x, A, out);
}